// round 1
// baseline (speedup 1.0000x reference)
#include <cuda_runtime.h>
#include <cuda_bf16.h>

// Problem constants
#define B 8
#define S 512
#define E 64
#define H 8          // heads
#define D 8          // d_k = n_wires
#define BH (B*H)     // 64

// Scratch: ctx in [b, s, h, d] layout = [4096, 64] rows for the projection.
__device__ float g_ctx[B * S * E];

// ---------------------------------------------------------------------------
// Kernel 1: fused quantum-head computation + self-attention (q = k = v).
//
// q[w=0]   = prod_{j=1..7} cos(x_j + th_j)
// q[w>=1]  = prod_{j=0..w} cos(x_j + th_j)
//
// One block = one (b,h) pair + one chunk of 128 queries.
// Block cooperatively builds the full 512x8 K tile in smem, then each thread
// handles one query: dot over 512 keys, exp (no max needed: |score| <= 2.83),
// weighted accumulation of V (= K).
// ---------------------------------------------------------------------------
__global__ __launch_bounds__(128) void qattn_kernel(
    const float* __restrict__ x,      // [B, S, E]
    const float* __restrict__ theta,  // [8]
    float* __restrict__ ctx)          // [B, S, H, D] (= [4096, 64])
{
    __shared__ float4 Ksm[S * 2];     // 512 rows x 8 floats (2x float4), 16 KB

    const int bh  = blockIdx.y;       // 0..63
    const int b   = bh >> 3;
    const int h   = bh & 7;
    const int tid = threadIdx.x;      // 0..127

    float th[8];
#pragma unroll
    for (int j = 0; j < 8; ++j) th[j] = __ldg(theta + j);

    const float* xb = x + ((size_t)b * S) * E + h * 8;

    // Build K tile: each thread computes 4 rows (512 / 128).
    for (int s = tid; s < S; s += 128) {
        float4 v0 = *(const float4*)(xb + (size_t)s * E);
        float4 v1 = *(const float4*)(xb + (size_t)s * E + 4);
        float c0 = cosf(v0.x + th[0]);
        float c1 = cosf(v0.y + th[1]);
        float c2 = cosf(v0.z + th[2]);
        float c3 = cosf(v0.w + th[3]);
        float c4 = cosf(v1.x + th[4]);
        float c5 = cosf(v1.y + th[5]);
        float c6 = cosf(v1.z + th[6]);
        float c7 = cosf(v1.w + th[7]);

        // suffix product for wire 0, prefix products for wires 1..7
        float q1 = c0 * c1;
        float q2 = q1 * c2;
        float q3 = q2 * c3;
        float q4 = q3 * c4;
        float q5 = q4 * c5;
        float q6 = q5 * c6;
        float q7 = q6 * c7;
        float q0 = c1 * c2 * c3 * c4 * c5 * c6 * c7;

        Ksm[s * 2 + 0] = make_float4(q0, q1, q2, q3);
        Ksm[s * 2 + 1] = make_float4(q4, q5, q6, q7);
    }
    __syncthreads();

    // Each thread: one query row.
    const int sq = blockIdx.x * 128 + tid;
    const float scale = 0.35355339059327373f; // 1/sqrt(8)

    float4 qa = Ksm[sq * 2 + 0];
    float4 qb = Ksm[sq * 2 + 1];
    // fold softmax scale into the query
    qa.x *= scale; qa.y *= scale; qa.z *= scale; qa.w *= scale;
    qb.x *= scale; qb.y *= scale; qb.z *= scale; qb.w *= scale;

    float acc0 = 0.f, acc1 = 0.f, acc2 = 0.f, acc3 = 0.f;
    float acc4 = 0.f, acc5 = 0.f, acc6 = 0.f, acc7 = 0.f;
    float l = 0.f;

#pragma unroll 4
    for (int j = 0; j < S; ++j) {
        float4 ka = Ksm[j * 2 + 0];   // broadcast across the warp
        float4 kb = Ksm[j * 2 + 1];
        float dot = qa.x * ka.x + qa.y * ka.y + qa.z * ka.z + qa.w * ka.w
                  + qb.x * kb.x + qb.y * kb.y + qb.z * kb.z + qb.w * kb.w;
        float w = __expf(dot);        // scores bounded by 2*sqrt(2): no max shift needed
        l += w;
        acc0 = fmaf(w, ka.x, acc0);
        acc1 = fmaf(w, ka.y, acc1);
        acc2 = fmaf(w, ka.z, acc2);
        acc3 = fmaf(w, ka.w, acc3);
        acc4 = fmaf(w, kb.x, acc4);
        acc5 = fmaf(w, kb.y, acc5);
        acc6 = fmaf(w, kb.z, acc6);
        acc7 = fmaf(w, kb.w, acc7);
    }

    float inv = 1.f / l;
    float* cp = ctx + ((size_t)(b * S + sq)) * E + h * 8;
    *(float4*)(cp + 0) = make_float4(acc0 * inv, acc1 * inv, acc2 * inv, acc3 * inv);
    *(float4*)(cp + 4) = make_float4(acc4 * inv, acc5 * inv, acc6 * inv, acc7 * inv);
}

// ---------------------------------------------------------------------------
// Kernel 2: output projection. out[n, e] = sum_k ctx[n, k] * W_o[e, k] + b_o[e]
// n in [0, 4096), e in [0, 64). Block handles 32 rows; W stored transposed in
// smem (Wt[k][e]) so the inner reads are conflict-free.
// ---------------------------------------------------------------------------
__global__ __launch_bounds__(256) void proj_kernel(
    const float* __restrict__ ctx,   // [4096, 64]
    const float* __restrict__ W,     // [64, 64] row-major (e, k)
    const float* __restrict__ bo,    // [64]
    float* __restrict__ out)         // [4096, 64]
{
    __shared__ float Wt[64][65];     // Wt[k][e] = W[e*64 + k]
    __shared__ float Cs[32][64];
    __shared__ float bs[64];

    const int tid  = threadIdx.x;    // 0..255
    const int row0 = blockIdx.x * 32;

    for (int i = tid; i < 64 * 64; i += 256) {
        int e = i >> 6, k = i & 63;
        Wt[k][e] = W[i];
    }
    if (tid < 64) bs[tid] = bo[tid];
    for (int i = tid; i < 32 * 64; i += 256) {
        int r = i >> 6, k = i & 63;
        Cs[r][k] = ctx[(size_t)(row0 + r) * 64 + k];
    }
    __syncthreads();

    for (int i = tid; i < 32 * 64; i += 256) {
        int r = i >> 6, e = i & 63;   // within a warp: r fixed -> Cs broadcast
        float sum = bs[e];
#pragma unroll
        for (int k = 0; k < 64; ++k)
            sum = fmaf(Cs[r][k], Wt[k][e], sum);
        out[(size_t)(row0 + r) * 64 + e] = sum;
    }
}

extern "C" void kernel_launch(void* const* d_in, const int* in_sizes, int n_in,
                              void* d_out, int out_size)
{
    const float* x     = (const float*)d_in[0];  // [8, 512, 64]
    const float* theta = (const float*)d_in[1];  // [8]
    const float* W_o   = (const float*)d_in[2];  // [64, 64]
    const float* b_o   = (const float*)d_in[3];  // [64]
    float* out = (float*)d_out;                  // [8, 512, 64]

    float* ctx;
    cudaGetSymbolAddress((void**)&ctx, g_ctx);

    dim3 grid1(S / 128, BH);     // (4, 64)
    qattn_kernel<<<grid1, 128>>>(x, theta, ctx);

    proj_kernel<<<(B * S) / 32, 256>>>(ctx, W_o, b_o, out);
}

// round 2
// speedup vs baseline: 1.6404x; 1.6404x over previous
#include <cuda_runtime.h>
#include <cuda_bf16.h>

#define B 8
#define S 512
#define E 64
#define H 8
#define D 8
#define BH (B*H)

__device__ float g_ctx[B * S * E];

// ---- packed f32x2 helpers (sm_103a) ---------------------------------------
__device__ __forceinline__ unsigned long long pk2(float lo, float hi) {
    unsigned long long r;
    asm("mov.b64 %0, {%1, %2};" : "=l"(r) : "f"(lo), "f"(hi));
    return r;
}
__device__ __forceinline__ void upk2(unsigned long long v, float& lo, float& hi) {
    asm("mov.b64 {%0, %1}, %2;" : "=f"(lo), "=f"(hi) : "l"(v));
}
__device__ __forceinline__ unsigned long long fma2(unsigned long long a,
                                                   unsigned long long b,
                                                   unsigned long long c) {
    unsigned long long d;
    asm("fma.rn.f32x2 %0, %1, %2, %3;" : "=l"(d) : "l"(a), "l"(b), "l"(c));
    return d;
}
__device__ __forceinline__ unsigned long long mul2(unsigned long long a,
                                                   unsigned long long b) {
    unsigned long long d;
    asm("mul.rn.f32x2 %0, %1, %2;" : "=l"(d) : "l"(a), "l"(b));
    return d;
}

// ---------------------------------------------------------------------------
// Kernel 1: quantum heads (analytic: prefix products of cosines) + attention.
// Block = (b,h) x 128-query chunk, 512 threads. 4 threads per query, each
// covering keys j = g + 4*i (interleaved -> conflict-free broadcast LDS).
// ---------------------------------------------------------------------------
__global__ __launch_bounds__(512) void qattn_kernel(
    const float* __restrict__ x,      // [B, S, E]
    const float* __restrict__ theta,  // [8]
    float* __restrict__ ctx)          // [B*S, 64]
{
    __shared__ __align__(16) float Ks[S * 8];   // 512 rows x 8 floats = 16 KB

    const int bh  = blockIdx.y;
    const int b   = bh >> 3;
    const int h   = bh & 7;
    const int tid = threadIdx.x;      // 0..511

    float th[8];
#pragma unroll
    for (int j = 0; j < 8; ++j) th[j] = __ldg(theta + j);

    // Build K: one row per thread.
    {
        const float* xr = x + ((size_t)(b * S + tid)) * E + h * 8;
        float4 v0 = *(const float4*)(xr);
        float4 v1 = *(const float4*)(xr + 4);
        float c0 = __cosf(v0.x + th[0]);
        float c1 = __cosf(v0.y + th[1]);
        float c2 = __cosf(v0.z + th[2]);
        float c3 = __cosf(v0.w + th[3]);
        float c4 = __cosf(v1.x + th[4]);
        float c5 = __cosf(v1.y + th[5]);
        float c6 = __cosf(v1.z + th[6]);
        float c7 = __cosf(v1.w + th[7]);
        float q1 = c0 * c1;
        float q2 = q1 * c2;
        float q3 = q2 * c3;
        float q4 = q3 * c4;
        float q5 = q4 * c5;
        float q6 = q5 * c6;
        float q7 = q6 * c7;
        float q0 = c1 * c2 * c3 * c4 * c5 * c6 * c7;
        ((float4*)Ks)[tid * 2 + 0] = make_float4(q0, q1, q2, q3);
        ((float4*)Ks)[tid * 2 + 1] = make_float4(q4, q5, q6, q7);
    }
    __syncthreads();

    const int q = blockIdx.x * 128 + (tid >> 2);  // query row
    const int g = tid & 3;                        // key-split lane

    // scale * log2(e) folded into q: exp(dot/sqrt(8)) = exp2(dot * sc)
    const float sc = 0.35355339059327373f * 1.4426950408889634f;
    float4 qa = ((const float4*)Ks)[q * 2 + 0];
    float4 qb = ((const float4*)Ks)[q * 2 + 1];
    unsigned long long q01 = pk2(qa.x * sc, qa.y * sc);
    unsigned long long q23 = pk2(qa.z * sc, qa.w * sc);
    unsigned long long q45 = pk2(qb.x * sc, qb.y * sc);
    unsigned long long q67 = pk2(qb.z * sc, qb.w * sc);

    unsigned long long acc01 = 0ull, acc23 = 0ull, acc45 = 0ull, acc67 = 0ull;
    float l = 0.f;

    const ulonglong2* Kp = (const ulonglong2*)Ks + g * 2;  // row g; 2 x 16B per row
#pragma unroll 4
    for (int i = 0; i < 128; ++i) {           // keys g, g+4, g+8, ...
        ulonglong2 kA = Kp[i * 8 + 0];        // (k0,k1),(k2,k3)
        ulonglong2 kB = Kp[i * 8 + 1];        // (k4,k5),(k6,k7)
        unsigned long long d2 =
            fma2(q01, kA.x, fma2(q23, kA.y, fma2(q45, kB.x, mul2(q67, kB.y))));
        float dl, dh; upk2(d2, dl, dh);
        float w;
        asm("ex2.approx.f32 %0, %1;" : "=f"(w) : "f"(dl + dh));
        l += w;
        unsigned long long w2 = pk2(w, w);
        acc01 = fma2(w2, kA.x, acc01);
        acc23 = fma2(w2, kA.y, acc23);
        acc45 = fma2(w2, kB.x, acc45);
        acc67 = fma2(w2, kB.y, acc67);
    }

    // reduce across the 4 split lanes (consecutive lanes within warp)
    float a[9];
    upk2(acc01, a[0], a[1]);
    upk2(acc23, a[2], a[3]);
    upk2(acc45, a[4], a[5]);
    upk2(acc67, a[6], a[7]);
    a[8] = l;
#pragma unroll
    for (int v = 0; v < 9; ++v) {
        a[v] += __shfl_xor_sync(0xffffffffu, a[v], 1);
        a[v] += __shfl_xor_sync(0xffffffffu, a[v], 2);
    }

    if (g == 0) {
        float inv = 1.f / a[8];
        float* cp = ctx + ((size_t)(b * S + q)) * E + h * 8;
        *(float4*)(cp + 0) = make_float4(a[0] * inv, a[1] * inv, a[2] * inv, a[3] * inv);
        *(float4*)(cp + 4) = make_float4(a[4] * inv, a[5] * inv, a[6] * inv, a[7] * inv);
    }
}

// ---------------------------------------------------------------------------
// Kernel 2: out = ctx @ W^T + b. 4x4 register tiles, float4 LDS, k-inner for
// both operands (no transpose). 128 threads, 32 rows/block, grid 128.
// ---------------------------------------------------------------------------
__global__ __launch_bounds__(128) void proj_kernel(
    const float* __restrict__ ctx,   // [4096, 64]
    const float* __restrict__ W,     // [64, 64]  (e, k)
    const float* __restrict__ bo,    // [64]
    float* __restrict__ out)         // [4096, 64]
{
    __shared__ __align__(16) float Ws[64][68];
    __shared__ __align__(16) float Cs[32][68];
    __shared__ float bs[64];

    const int tid  = threadIdx.x;     // 0..127
    const int row0 = blockIdx.x * 32;

    for (int i = tid * 4; i < 64 * 64; i += 128 * 4) {
        float4 w = *(const float4*)(W + i);
        *(float4*)&Ws[i >> 6][i & 63] = w;
    }
    for (int i = tid * 4; i < 32 * 64; i += 128 * 4) {
        float4 c = *(const float4*)(ctx + (size_t)row0 * 64 + i);
        *(float4*)&Cs[i >> 6][i & 63] = c;
    }
    if (tid < 64) bs[tid] = bo[tid];
    __syncthreads();

    const int rt = tid >> 4;          // 0..7
    const int et = tid & 15;          // 0..15
    const int r0 = rt * 4, e0 = et * 4;

    float acc[4][4] = {};
#pragma unroll
    for (int it = 0; it < 16; ++it) {
        int k0 = ((it + et) & 15) * 4;   // lane-rotated k to spread banks
        float4 c[4], w[4];
#pragma unroll
        for (int j = 0; j < 4; ++j) c[j] = *(const float4*)&Cs[r0 + j][k0];
#pragma unroll
        for (int j = 0; j < 4; ++j) w[j] = *(const float4*)&Ws[e0 + j][k0];
#pragma unroll
        for (int ri = 0; ri < 4; ++ri)
#pragma unroll
            for (int ei = 0; ei < 4; ++ei) {
                acc[ri][ei] = fmaf(c[ri].x, w[ei].x, acc[ri][ei]);
                acc[ri][ei] = fmaf(c[ri].y, w[ei].y, acc[ri][ei]);
                acc[ri][ei] = fmaf(c[ri].z, w[ei].z, acc[ri][ei]);
                acc[ri][ei] = fmaf(c[ri].w, w[ei].w, acc[ri][ei]);
            }
    }

#pragma unroll
    for (int ri = 0; ri < 4; ++ri) {
        float4 o = make_float4(acc[ri][0] + bs[e0 + 0],
                               acc[ri][1] + bs[e0 + 1],
                               acc[ri][2] + bs[e0 + 2],
                               acc[ri][3] + bs[e0 + 3]);
        *(float4*)(out + (size_t)(row0 + r0 + ri) * 64 + e0) = o;
    }
}

extern "C" void kernel_launch(void* const* d_in, const int* in_sizes, int n_in,
                              void* d_out, int out_size)
{
    const float* x     = (const float*)d_in[0];  // [8, 512, 64]
    const float* theta = (const float*)d_in[1];  // [8]
    const float* W_o   = (const float*)d_in[2];  // [64, 64]
    const float* b_o   = (const float*)d_in[3];  // [64]
    float* out = (float*)d_out;

    float* ctx;
    cudaGetSymbolAddress((void**)&ctx, g_ctx);

    dim3 grid1(S / 128, BH);             // (4, 64)
    qattn_kernel<<<grid1, 512>>>(x, theta, ctx);

    proj_kernel<<<(B * S) / 32, 128>>>(ctx, W_o, b_o, out);
}